// round 2
// baseline (speedup 1.0000x reference)
#include <cuda_runtime.h>
#include <math.h>

#define Nn 50000
#define Ee 800000
#define Cc 100000
#define D 128
#define NEG 0.01f
#define BN_EPS 1e-5f

// ---------------- scratch (static __device__, no allocation) ----------------
__device__ float g_h0[(size_t)Nn * D];
__device__ float g_h1[(size_t)Nn * D];
__device__ float g_agg[(size_t)Nn * D];
__device__ int   g_deg[Nn];
__device__ int   g_off[Nn + 1];
__device__ int   g_cur[Nn];
__device__ int   g_csr[Ee];
__device__ int   g_bsum[64];
__device__ float g_part[256];
__device__ float g_max_v;
__device__ float g_sum_v;

// ---------------- CSR build ----------------
__global__ void k_zero_deg() {
    int i = blockIdx.x * blockDim.x + threadIdx.x;
    if (i < Nn) g_deg[i] = 0;
}

__global__ void k_count(const int* __restrict__ dst, int E) {
    for (int e = blockIdx.x * blockDim.x + threadIdx.x; e < E; e += gridDim.x * blockDim.x)
        atomicAdd(&g_deg[dst[e]], 1);
}

__global__ void k_scan_partial() {
    __shared__ int sm[1024];
    int i = blockIdx.x * 1024 + threadIdx.x;
    int v = (i < Nn) ? g_deg[i] : 0;
    sm[threadIdx.x] = v;
    __syncthreads();
    for (int s = 1; s < 1024; s <<= 1) {
        int t = (threadIdx.x >= s) ? sm[threadIdx.x - s] : 0;
        __syncthreads();
        sm[threadIdx.x] += t;
        __syncthreads();
    }
    if (i < Nn) g_off[i + 1] = sm[threadIdx.x];
    if (threadIdx.x == 1023) g_bsum[blockIdx.x] = sm[1023];
}

__global__ void k_scan_bsum(int nb) {
    if (threadIdx.x == 0) {
        int acc = 0;
        for (int i = 0; i < nb; i++) { int t = g_bsum[i]; g_bsum[i] = acc; acc += t; }
    }
}

__global__ void k_scan_add() {
    int i = blockIdx.x * 1024 + threadIdx.x;
    if (i < Nn) g_off[i + 1] += g_bsum[blockIdx.x];
    if (i == 0) g_off[0] = 0;
}

__global__ void k_copy_cur() {
    int i = blockIdx.x * blockDim.x + threadIdx.x;
    if (i < Nn) g_cur[i] = g_off[i];
}

__global__ void k_fill(const int* __restrict__ src, const int* __restrict__ dst, int E) {
    for (int e = blockIdx.x * blockDim.x + threadIdx.x; e < E; e += gridDim.x * blockDim.x) {
        int d = dst[e];
        int p = atomicAdd(&g_cur[d], 1);
        g_csr[p] = src[e];
    }
}

// ---------------- segment-mean aggregation (warp per node) ----------------
__global__ void k_agg(const float* __restrict__ A, float* __restrict__ out) {
    int w = threadIdx.x >> 5, l = threadIdx.x & 31;
    int node = blockIdx.x * 8 + w;
    if (node >= Nn) return;
    int s = g_off[node], e = g_off[node + 1];
    float4 acc = make_float4(0.f, 0.f, 0.f, 0.f);
    for (int i = s; i < e; i++) {
        int sr = g_csr[i];
        float4 v = ((const float4*)(A + (size_t)sr * D))[l];
        acc.x += v.x; acc.y += v.y; acc.z += v.z; acc.w += v.w;
    }
    int deg = e - s;
    float inv = 1.0f / (float)(deg > 1 ? deg : 1);
    acc.x *= inv; acc.y *= inv; acc.z *= inv; acc.w *= inv;
    ((float4*)(out + (size_t)node * D))[l] = acc;
}

// ---------------- SAGE GEMM + BN + leaky (fused) ----------------
__global__ void k_gemm(const float* __restrict__ A, const float* __restrict__ G,
                       const float* __restrict__ Ws, const float* __restrict__ Wn,
                       const float* __restrict__ bias, const float* __restrict__ gamma,
                       const float* __restrict__ beta, const float* __restrict__ rm,
                       const float* __restrict__ rv, float* __restrict__ out, int fixnan) {
    extern __shared__ float sm[];
    float* sWs = sm;            // 128*128
    float* sWn = sm + 16384;    // 128*128
    {
        float4* d0 = (float4*)sWs; const float4* s0 = (const float4*)Ws;
        float4* d1 = (float4*)sWn; const float4* s1 = (const float4*)Wn;
        for (int i = threadIdx.x; i < 4096; i += 256) { d0[i] = s0[i]; d1[i] = s1[i]; }
    }
    __syncthreads();
    int w = threadIdx.x >> 5, l = threadIdx.x & 31;
    int n0 = blockIdx.x * 16 + w * 2;
    if (n0 >= Nn) return;
    int n1 = n0 + 1;
    float acc0[4] = {0.f, 0.f, 0.f, 0.f};
    float acc1[4] = {0.f, 0.f, 0.f, 0.f};
    const float4* a0 = (const float4*)(A + (size_t)n0 * D);
    const float4* a1 = (const float4*)(A + (size_t)n1 * D);
    const float4* g0 = (const float4*)(G + (size_t)n0 * D);
    const float4* g1 = (const float4*)(G + (size_t)n1 * D);
    int c = l * 4;
#pragma unroll 4
    for (int k4 = 0; k4 < 32; k4++) {
        float4 xs0 = a0[k4], xs1 = a1[k4], xg0 = g0[k4], xg1 = g1[k4];
        int kb = k4 * 4;
#pragma unroll
        for (int kk = 0; kk < 4; kk++) {
            float4 ws = *(const float4*)&sWs[(kb + kk) * D + c];
            float4 wn = *(const float4*)&sWn[(kb + kk) * D + c];
            float vs0 = ((const float*)&xs0)[kk], vs1 = ((const float*)&xs1)[kk];
            float vg0 = ((const float*)&xg0)[kk], vg1 = ((const float*)&xg1)[kk];
            acc0[0] = fmaf(vs0, ws.x, acc0[0]); acc0[0] = fmaf(vg0, wn.x, acc0[0]);
            acc0[1] = fmaf(vs0, ws.y, acc0[1]); acc0[1] = fmaf(vg0, wn.y, acc0[1]);
            acc0[2] = fmaf(vs0, ws.z, acc0[2]); acc0[2] = fmaf(vg0, wn.z, acc0[2]);
            acc0[3] = fmaf(vs0, ws.w, acc0[3]); acc0[3] = fmaf(vg0, wn.w, acc0[3]);
            acc1[0] = fmaf(vs1, ws.x, acc1[0]); acc1[0] = fmaf(vg1, wn.x, acc1[0]);
            acc1[1] = fmaf(vs1, ws.y, acc1[1]); acc1[1] = fmaf(vg1, wn.y, acc1[1]);
            acc1[2] = fmaf(vs1, ws.z, acc1[2]); acc1[2] = fmaf(vg1, wn.z, acc1[2]);
            acc1[3] = fmaf(vs1, ws.w, acc1[3]); acc1[3] = fmaf(vg1, wn.w, acc1[3]);
        }
    }
    float4 bb = *(const float4*)&bias[c];
    float4 ga = *(const float4*)&gamma[c];
    float4 be = *(const float4*)&beta[c];
    float4 rmv = *(const float4*)&rm[c];
    float4 rvv = *(const float4*)&rv[c];
    float sc[4], sh[4];
    sc[0] = ga.x * rsqrtf(rvv.x + BN_EPS); sh[0] = be.x - rmv.x * sc[0];
    sc[1] = ga.y * rsqrtf(rvv.y + BN_EPS); sh[1] = be.y - rmv.y * sc[1];
    sc[2] = ga.z * rsqrtf(rvv.z + BN_EPS); sh[2] = be.z - rmv.z * sc[2];
    sc[3] = ga.w * rsqrtf(rvv.w + BN_EPS); sh[3] = be.w - rmv.w * sc[3];
    const float* bbp = (const float*)&bb;
    float o0[4], o1[4];
#pragma unroll
    for (int j = 0; j < 4; j++) {
        float v = acc0[j] + bbp[j];
        v = v * sc[j] + sh[j];
        v = v >= 0.f ? v : NEG * v;
        if (fixnan) {
            if (isnan(v)) v = 1e-14f;
            else if (isinf(v)) v = v > 0.f ? 3.402823466e38f : -3.402823466e38f;
        }
        o0[j] = v;
    }
#pragma unroll
    for (int j = 0; j < 4; j++) {
        float v = acc1[j] + bbp[j];
        v = v * sc[j] + sh[j];
        v = v >= 0.f ? v : NEG * v;
        if (fixnan) {
            if (isnan(v)) v = 1e-14f;
            else if (isinf(v)) v = v > 0.f ? 3.402823466e38f : -3.402823466e38f;
        }
        o1[j] = v;
    }
    *(float4*)&out[(size_t)n0 * D + c] = make_float4(o0[0], o0[1], o0[2], o0[3]);
    *(float4*)&out[(size_t)n1 * D + c] = make_float4(o1[0], o1[1], o1[2], o1[3]);
}

// ---------------- candidate MLP (warp per candidate) ----------------
// smem layout (floats, all offsets multiples of 4 for float4 ops):
//   sw0:    [0, 16448)
//   sw1:    [16448, 20544)
//   sb0:    [20544, 20608)
//   sb1:    [20608, 20672)
//   sw2:    [20672, 20736)
//   sb2:    [20736, 20752)   (16 floats pad -> inbuf 16B-aligned)
//   inbuf:  [20752, 20752+8*260)   per-warp 260 floats (1040B, 16B-aligned)
//   z1b:    [22832, 22832+8*64)
// total = 23344 floats = 93376 bytes
__global__ void k_mlp(const float* __restrict__ h, const int* __restrict__ cu,
                      const int* __restrict__ cv, const float* __restrict__ cf,
                      const float* __restrict__ mw0, const float* __restrict__ mb0,
                      const float* __restrict__ mw1, const float* __restrict__ mb1,
                      const float* __restrict__ mw2, const float* __restrict__ mb2,
                      float* __restrict__ y, int C) {
    extern __shared__ float sm[];
    float* sw0 = sm;
    float* sw1 = sm + 16448;
    float* sb0 = sm + 20544;
    float* sb1 = sm + 20608;
    float* sw2 = sm + 20672;
    float* sb2 = sm + 20736;
    float* inbuf = sm + 20752;
    float* z1b = sm + 22832;
    for (int i = threadIdx.x; i < 16448; i += 256) sw0[i] = mw0[i];
    for (int i = threadIdx.x; i < 4096; i += 256) sw1[i] = mw1[i];
    if (threadIdx.x < 64) {
        sb0[threadIdx.x] = mb0[threadIdx.x];
        sb1[threadIdx.x] = mb1[threadIdx.x];
        sw2[threadIdx.x] = mw2[threadIdx.x];
    }
    if (threadIdx.x == 0) sb2[0] = mb2[0];
    __syncthreads();
    int w = threadIdx.x >> 5, l = threadIdx.x & 31;
    float* inp = inbuf + w * 260;
    float* zz = z1b + w * 64;
    int l2 = 2 * l;
    for (int c = blockIdx.x * 8 + w; c < C; c += gridDim.x * 8) {
        int u = cu[c], v = cv[c];
        ((float4*)inp)[l] = ((const float4*)(h + (size_t)u * D))[l];
        ((float4*)(inp + 128))[l] = ((const float4*)(h + (size_t)v * D))[l];
        if (l == 0) inp[256] = cf[c];
        __syncwarp();
        float a0 = sb0[l2], a1 = sb0[l2 + 1];
#pragma unroll 8
        for (int k = 0; k < 256; k += 4) {
            float4 iv = *(const float4*)(inp + k);
            float2 w0v = *(const float2*)&sw0[(k + 0) * 64 + l2]; a0 = fmaf(iv.x, w0v.x, a0); a1 = fmaf(iv.x, w0v.y, a1);
            float2 w1v = *(const float2*)&sw0[(k + 1) * 64 + l2]; a0 = fmaf(iv.y, w1v.x, a0); a1 = fmaf(iv.y, w1v.y, a1);
            float2 w2v = *(const float2*)&sw0[(k + 2) * 64 + l2]; a0 = fmaf(iv.z, w2v.x, a0); a1 = fmaf(iv.z, w2v.y, a1);
            float2 w3v = *(const float2*)&sw0[(k + 3) * 64 + l2]; a0 = fmaf(iv.w, w3v.x, a0); a1 = fmaf(iv.w, w3v.y, a1);
        }
        {
            float fin = inp[256];
            float2 wv = *(const float2*)&sw0[256 * 64 + l2];
            a0 = fmaf(fin, wv.x, a0); a1 = fmaf(fin, wv.y, a1);
        }
        a0 = a0 >= 0.f ? a0 : NEG * a0;
        a1 = a1 >= 0.f ? a1 : NEG * a1;
        zz[l2] = a0; zz[l2 + 1] = a1;
        __syncwarp();
        float b0 = sb1[l2], b1 = sb1[l2 + 1];
#pragma unroll
        for (int k = 0; k < 64; k += 4) {
            float4 iv = *(const float4*)(zz + k);
            float2 w0v = *(const float2*)&sw1[(k + 0) * 64 + l2]; b0 = fmaf(iv.x, w0v.x, b0); b1 = fmaf(iv.x, w0v.y, b1);
            float2 w1v = *(const float2*)&sw1[(k + 1) * 64 + l2]; b0 = fmaf(iv.y, w1v.x, b0); b1 = fmaf(iv.y, w1v.y, b1);
            float2 w2v = *(const float2*)&sw1[(k + 2) * 64 + l2]; b0 = fmaf(iv.z, w2v.x, b0); b1 = fmaf(iv.z, w2v.y, b1);
            float2 w3v = *(const float2*)&sw1[(k + 3) * 64 + l2]; b0 = fmaf(iv.w, w3v.x, b0); b1 = fmaf(iv.w, w3v.y, b1);
        }
        b0 = b0 >= 0.f ? b0 : NEG * b0;
        b1 = b1 >= 0.f ? b1 : NEG * b1;
        float p = b0 * sw2[l2] + b1 * sw2[l2 + 1];
#pragma unroll
        for (int o = 16; o; o >>= 1) p += __shfl_xor_sync(0xffffffffu, p, o);
        if (l == 0) y[c] = p + sb2[0];
        __syncwarp();
    }
}

// ---------------- softmax over C (deterministic tree reductions) ----------------
__global__ void k_rmax(const float* __restrict__ y, int C) {
    __shared__ float sm[256];
    float m = -3.402823466e38f;
    for (int i = blockIdx.x * 256 + threadIdx.x; i < C; i += gridDim.x * 256)
        m = fmaxf(m, y[i]);
    sm[threadIdx.x] = m;
    __syncthreads();
    for (int s = 128; s; s >>= 1) {
        if (threadIdx.x < s) sm[threadIdx.x] = fmaxf(sm[threadIdx.x], sm[threadIdx.x + s]);
        __syncthreads();
    }
    if (threadIdx.x == 0) g_part[blockIdx.x] = sm[0];
}

__global__ void k_rmax_fin(int nb) {
    __shared__ float sm[256];
    float m = -3.402823466e38f;
    if (threadIdx.x < nb) m = g_part[threadIdx.x];
    sm[threadIdx.x] = m;
    __syncthreads();
    for (int s = 128; s; s >>= 1) {
        if (threadIdx.x < s) sm[threadIdx.x] = fmaxf(sm[threadIdx.x], sm[threadIdx.x + s]);
        __syncthreads();
    }
    if (threadIdx.x == 0) g_max_v = sm[0];
}

__global__ void k_rsum(const float* __restrict__ y, int C) {
    __shared__ float sm[256];
    float mx = g_max_v;
    float s = 0.f;
    for (int i = blockIdx.x * 256 + threadIdx.x; i < C; i += gridDim.x * 256)
        s += expf(y[i] - mx);
    sm[threadIdx.x] = s;
    __syncthreads();
    for (int st = 128; st; st >>= 1) {
        if (threadIdx.x < st) sm[threadIdx.x] += sm[threadIdx.x + st];
        __syncthreads();
    }
    if (threadIdx.x == 0) g_part[blockIdx.x] = sm[0];
}

__global__ void k_rsum_fin(int nb) {
    __shared__ float sm[256];
    float s = (threadIdx.x < nb) ? g_part[threadIdx.x] : 0.f;
    sm[threadIdx.x] = s;
    __syncthreads();
    for (int st = 128; st; st >>= 1) {
        if (threadIdx.x < st) sm[threadIdx.x] += sm[threadIdx.x + st];
        __syncthreads();
    }
    if (threadIdx.x == 0) g_sum_v = sm[0];
}

__global__ void k_soft(const float* __restrict__ y, float* __restrict__ out, int C) {
    float mx = g_max_v;
    float inv = 1.0f / g_sum_v;
    for (int i = blockIdx.x * 256 + threadIdx.x; i < C; i += gridDim.x * 256)
        out[i] = expf(y[i] - mx) * inv;
}

// ---------------- host launcher ----------------
extern "C" void kernel_launch(void* const* d_in, const int* in_sizes, int n_in,
                              void* d_out, int out_size) {
    const float* x   = (const float*)d_in[0];
    const int* src   = (const int*)d_in[1];
    const int* dst   = (const int*)d_in[2];
    const int* cu    = (const int*)d_in[3];
    const int* cv    = (const int*)d_in[4];
    const float* cf  = (const float*)d_in[5];
    const float* ws0 = (const float*)d_in[6];
    const float* wn0 = (const float*)d_in[7];
    const float* b0  = (const float*)d_in[8];
    const float* ga0 = (const float*)d_in[9];
    const float* be0 = (const float*)d_in[10];
    const float* rm0 = (const float*)d_in[11];
    const float* rv0 = (const float*)d_in[12];
    const float* ws1 = (const float*)d_in[13];
    const float* wn1 = (const float*)d_in[14];
    const float* b1  = (const float*)d_in[15];
    const float* ga1 = (const float*)d_in[16];
    const float* be1 = (const float*)d_in[17];
    const float* rm1 = (const float*)d_in[18];
    const float* rv1 = (const float*)d_in[19];
    const float* mw0 = (const float*)d_in[20];
    const float* mb0 = (const float*)d_in[21];
    const float* mw1 = (const float*)d_in[22];
    const float* mb1 = (const float*)d_in[23];
    const float* mw2 = (const float*)d_in[24];
    const float* mb2 = (const float*)d_in[25];

    int E = in_sizes[1];
    int C = in_sizes[3];
    float* y = (float*)d_out;
    float* soft = y + C;

    float *h0p, *h1p, *aggp;
    cudaGetSymbolAddress((void**)&h0p, g_h0);
    cudaGetSymbolAddress((void**)&h1p, g_h1);
    cudaGetSymbolAddress((void**)&aggp, g_agg);

    cudaFuncSetAttribute(k_gemm, cudaFuncAttributeMaxDynamicSharedMemorySize, 131072);
    cudaFuncSetAttribute(k_mlp, cudaFuncAttributeMaxDynamicSharedMemorySize, 93376);

    const int NB_SCAN = (Nn + 1023) / 1024;  // 49

    // CSR build (once per call; reused by both layers)
    k_zero_deg<<<(Nn + 255) / 256, 256>>>();
    k_count<<<1024, 256>>>(dst, E);
    k_scan_partial<<<NB_SCAN, 1024>>>();
    k_scan_bsum<<<1, 32>>>(NB_SCAN);
    k_scan_add<<<NB_SCAN, 1024>>>();
    k_copy_cur<<<(Nn + 255) / 256, 256>>>();
    k_fill<<<1024, 256>>>(src, dst, E);

    // layer 0
    k_agg<<<(Nn + 7) / 8, 256>>>(x, aggp);
    k_gemm<<<(Nn + 15) / 16, 256, 131072>>>(x, aggp, ws0, wn0, b0, ga0, be0, rm0, rv0, h0p, 0);

    // layer 1 (+ nan_to_num fused)
    k_agg<<<(Nn + 7) / 8, 256>>>(h0p, aggp);
    k_gemm<<<(Nn + 15) / 16, 256, 131072>>>(h0p, aggp, ws1, wn1, b1, ga1, be1, rm1, rv1, h1p, 1);

    // candidate MLP -> y
    k_mlp<<<2048, 256, 93376>>>(h1p, cu, cv, cf, mw0, mb0, mw1, mb1, mw2, mb2, y, C);

    // softmax over C
    k_rmax<<<256, 256>>>(y, C);
    k_rmax_fin<<<1, 256>>>(256);
    k_rsum<<<256, 256>>>(y, C);
    k_rsum_fin<<<1, 256>>>(256);
    k_soft<<<256, 256>>>(y, soft, C);
}

// round 3
// speedup vs baseline: 1.2880x; 1.2880x over previous
#include <cuda_runtime.h>
#include <math.h>

#define Nn 50000
#define Ee 800000
#define Cc 100000
#define D 128
#define NEG 0.01f
#define BN_EPS 1e-5f

// ---------------- scratch (static __device__, no allocation) ----------------
__device__ float g_h0[(size_t)Nn * D];
__device__ float g_h1[(size_t)Nn * D];
__device__ float g_agg[(size_t)Nn * D];
__device__ float g_pu[(size_t)Nn * 64];
__device__ float g_pv[(size_t)Nn * 64];
__device__ int   g_deg[Nn];
__device__ int   g_off[Nn + 1];
__device__ int   g_cur[Nn];
__device__ int   g_csr[Ee];
__device__ int   g_bsum[64];
__device__ float g_part[256];
__device__ float g_max_v;
__device__ float g_sum_v;

// ---------------- CSR build ----------------
__global__ void k_zero_deg() {
    int i = blockIdx.x * blockDim.x + threadIdx.x;
    if (i < Nn) g_deg[i] = 0;
}

__global__ void k_count(const int* __restrict__ dst, int E) {
    for (int e = blockIdx.x * blockDim.x + threadIdx.x; e < E; e += gridDim.x * blockDim.x)
        atomicAdd(&g_deg[dst[e]], 1);
}

// shfl-based block scan (1024 threads)
__global__ void k_scan_partial() {
    __shared__ int ws[32];
    int i = blockIdx.x * 1024 + threadIdx.x;
    int lane = threadIdx.x & 31, wid = threadIdx.x >> 5;
    int v = (i < Nn) ? g_deg[i] : 0;
    int s = v;
#pragma unroll
    for (int o = 1; o < 32; o <<= 1) {
        int t = __shfl_up_sync(0xffffffffu, s, o);
        if (lane >= o) s += t;
    }
    if (lane == 31) ws[wid] = s;
    __syncthreads();
    if (wid == 0) {
        int t = ws[lane];
#pragma unroll
        for (int o = 1; o < 32; o <<= 1) {
            int u = __shfl_up_sync(0xffffffffu, t, o);
            if (lane >= o) t += u;
        }
        ws[lane] = t;
    }
    __syncthreads();
    int off = wid ? ws[wid - 1] : 0;
    s += off;
    if (i < Nn) g_off[i + 1] = s;
    if (threadIdx.x == 1023) g_bsum[blockIdx.x] = s;
}

__global__ void k_scan_bsum(int nb) {
    if (threadIdx.x == 0) {
        int acc = 0;
        for (int i = 0; i < nb; i++) { int t = g_bsum[i]; g_bsum[i] = acc; acc += t; }
    }
}

__global__ void k_scan_add() {
    int i = blockIdx.x * 1024 + threadIdx.x;
    if (i < Nn) g_off[i + 1] += g_bsum[blockIdx.x];
    if (i == 0) g_off[0] = 0;
}

__global__ void k_copy_cur() {
    int i = blockIdx.x * blockDim.x + threadIdx.x;
    if (i < Nn) g_cur[i] = g_off[i];
}

__global__ void k_fill(const int* __restrict__ src, const int* __restrict__ dst, int E) {
    for (int e = blockIdx.x * blockDim.x + threadIdx.x; e < E; e += gridDim.x * blockDim.x) {
        int d = dst[e];
        int p = atomicAdd(&g_cur[d], 1);
        g_csr[p] = src[e];
    }
}

// ---------------- segment-mean aggregation (warp per node, 4-way unrolled) ----------------
__global__ void k_agg(const float* __restrict__ A, float* __restrict__ out) {
    int w = threadIdx.x >> 5, l = threadIdx.x & 31;
    int node = blockIdx.x * 8 + w;
    if (node >= Nn) return;
    int s = g_off[node], e = g_off[node + 1];
    float4 a0 = make_float4(0.f, 0.f, 0.f, 0.f);
    float4 a1 = make_float4(0.f, 0.f, 0.f, 0.f);
    float4 a2 = make_float4(0.f, 0.f, 0.f, 0.f);
    float4 a3 = make_float4(0.f, 0.f, 0.f, 0.f);
    int i = s;
    for (; i + 4 <= e; i += 4) {
        int s0 = g_csr[i], s1 = g_csr[i + 1], s2 = g_csr[i + 2], s3 = g_csr[i + 3];
        float4 v0 = ((const float4*)(A + (size_t)s0 * D))[l];
        float4 v1 = ((const float4*)(A + (size_t)s1 * D))[l];
        float4 v2 = ((const float4*)(A + (size_t)s2 * D))[l];
        float4 v3 = ((const float4*)(A + (size_t)s3 * D))[l];
        a0.x += v0.x; a0.y += v0.y; a0.z += v0.z; a0.w += v0.w;
        a1.x += v1.x; a1.y += v1.y; a1.z += v1.z; a1.w += v1.w;
        a2.x += v2.x; a2.y += v2.y; a2.z += v2.z; a2.w += v2.w;
        a3.x += v3.x; a3.y += v3.y; a3.z += v3.z; a3.w += v3.w;
    }
    for (; i < e; i++) {
        int sr = g_csr[i];
        float4 v = ((const float4*)(A + (size_t)sr * D))[l];
        a0.x += v.x; a0.y += v.y; a0.z += v.z; a0.w += v.w;
    }
    a0.x += a1.x + a2.x + a3.x;
    a0.y += a1.y + a2.y + a3.y;
    a0.z += a1.z + a2.z + a3.z;
    a0.w += a1.w + a2.w + a3.w;
    int deg = e - s;
    float inv = 1.0f / (float)(deg > 1 ? deg : 1);
    a0.x *= inv; a0.y *= inv; a0.z *= inv; a0.w *= inv;
    ((float4*)(out + (size_t)node * D))[l] = a0;
}

// ---------------- SAGE GEMM + BN + leaky (fused) ----------------
__global__ void k_gemm(const float* __restrict__ A, const float* __restrict__ G,
                       const float* __restrict__ Ws, const float* __restrict__ Wn,
                       const float* __restrict__ bias, const float* __restrict__ gamma,
                       const float* __restrict__ beta, const float* __restrict__ rm,
                       const float* __restrict__ rv, float* __restrict__ out, int fixnan) {
    extern __shared__ float sm[];
    float* sWs = sm;            // 128*128
    float* sWn = sm + 16384;    // 128*128
    {
        float4* d0 = (float4*)sWs; const float4* s0 = (const float4*)Ws;
        float4* d1 = (float4*)sWn; const float4* s1 = (const float4*)Wn;
        for (int i = threadIdx.x; i < 4096; i += 256) { d0[i] = s0[i]; d1[i] = s1[i]; }
    }
    __syncthreads();
    int w = threadIdx.x >> 5, l = threadIdx.x & 31;
    int n0 = blockIdx.x * 16 + w * 2;
    if (n0 >= Nn) return;
    int n1 = n0 + 1;
    float acc0[4] = {0.f, 0.f, 0.f, 0.f};
    float acc1[4] = {0.f, 0.f, 0.f, 0.f};
    const float4* a0 = (const float4*)(A + (size_t)n0 * D);
    const float4* a1 = (const float4*)(A + (size_t)n1 * D);
    const float4* g0 = (const float4*)(G + (size_t)n0 * D);
    const float4* g1 = (const float4*)(G + (size_t)n1 * D);
    int c = l * 4;
#pragma unroll 4
    for (int k4 = 0; k4 < 32; k4++) {
        float4 xs0 = a0[k4], xs1 = a1[k4], xg0 = g0[k4], xg1 = g1[k4];
        int kb = k4 * 4;
#pragma unroll
        for (int kk = 0; kk < 4; kk++) {
            float4 ws = *(const float4*)&sWs[(kb + kk) * D + c];
            float4 wn = *(const float4*)&sWn[(kb + kk) * D + c];
            float vs0 = ((const float*)&xs0)[kk], vs1 = ((const float*)&xs1)[kk];
            float vg0 = ((const float*)&xg0)[kk], vg1 = ((const float*)&xg1)[kk];
            acc0[0] = fmaf(vs0, ws.x, acc0[0]); acc0[0] = fmaf(vg0, wn.x, acc0[0]);
            acc0[1] = fmaf(vs0, ws.y, acc0[1]); acc0[1] = fmaf(vg0, wn.y, acc0[1]);
            acc0[2] = fmaf(vs0, ws.z, acc0[2]); acc0[2] = fmaf(vg0, wn.z, acc0[2]);
            acc0[3] = fmaf(vs0, ws.w, acc0[3]); acc0[3] = fmaf(vg0, wn.w, acc0[3]);
            acc1[0] = fmaf(vs1, ws.x, acc1[0]); acc1[0] = fmaf(vg1, wn.x, acc1[0]);
            acc1[1] = fmaf(vs1, ws.y, acc1[1]); acc1[1] = fmaf(vg1, wn.y, acc1[1]);
            acc1[2] = fmaf(vs1, ws.z, acc1[2]); acc1[2] = fmaf(vg1, wn.z, acc1[2]);
            acc1[3] = fmaf(vs1, ws.w, acc1[3]); acc1[3] = fmaf(vg1, wn.w, acc1[3]);
        }
    }
    float4 bb = *(const float4*)&bias[c];
    float4 ga = *(const float4*)&gamma[c];
    float4 be = *(const float4*)&beta[c];
    float4 rmv = *(const float4*)&rm[c];
    float4 rvv = *(const float4*)&rv[c];
    float sc[4], sh[4];
    sc[0] = ga.x * rsqrtf(rvv.x + BN_EPS); sh[0] = be.x - rmv.x * sc[0];
    sc[1] = ga.y * rsqrtf(rvv.y + BN_EPS); sh[1] = be.y - rmv.y * sc[1];
    sc[2] = ga.z * rsqrtf(rvv.z + BN_EPS); sh[2] = be.z - rmv.z * sc[2];
    sc[3] = ga.w * rsqrtf(rvv.w + BN_EPS); sh[3] = be.w - rmv.w * sc[3];
    const float* bbp = (const float*)&bb;
    float o0[4], o1[4];
#pragma unroll
    for (int j = 0; j < 4; j++) {
        float v = acc0[j] + bbp[j];
        v = v * sc[j] + sh[j];
        v = v >= 0.f ? v : NEG * v;
        if (fixnan) {
            if (isnan(v)) v = 1e-14f;
            else if (isinf(v)) v = v > 0.f ? 3.402823466e38f : -3.402823466e38f;
        }
        o0[j] = v;
    }
#pragma unroll
    for (int j = 0; j < 4; j++) {
        float v = acc1[j] + bbp[j];
        v = v * sc[j] + sh[j];
        v = v >= 0.f ? v : NEG * v;
        if (fixnan) {
            if (isnan(v)) v = 1e-14f;
            else if (isinf(v)) v = v > 0.f ? 3.402823466e38f : -3.402823466e38f;
        }
        o1[j] = v;
    }
    *(float4*)&out[(size_t)n0 * D + c] = make_float4(o0[0], o0[1], o0[2], o0[3]);
    *(float4*)&out[(size_t)n1 * D + c] = make_float4(o1[0], o1[1], o1[2], o1[3]);
}

// ---------------- node-level MLP layer0 projection ----------------
// Pu = h @ mw0[0:128,:], Pv = h @ mw0[128:256,:]   (bias/feat handled in k_cand)
__global__ void k_prep(const float* __restrict__ h, const float* __restrict__ mw0,
                       float* __restrict__ pu, float* __restrict__ pv) {
    extern __shared__ float sm[];  // 16384 floats: [0:8192)=rows0..127, [8192:16384)=rows128..255
    {
        float4* d = (float4*)sm; const float4* s = (const float4*)mw0;
        for (int i = threadIdx.x; i < 4096; i += 256) d[i] = s[i];
    }
    __syncthreads();
    int w = threadIdx.x >> 5, l = threadIdx.x & 31;
    int n0 = blockIdx.x * 16 + w * 2;
    if (n0 >= Nn) return;
    int n1 = n0 + 1;
    float au0x = 0.f, au0y = 0.f, au1x = 0.f, au1y = 0.f;
    float av0x = 0.f, av0y = 0.f, av1x = 0.f, av1y = 0.f;
    const float4* h0 = (const float4*)(h + (size_t)n0 * D);
    const float4* h1 = (const float4*)(h + (size_t)n1 * D);
    int c = l * 2;
#pragma unroll 4
    for (int k4 = 0; k4 < 32; k4++) {
        float4 x0 = h0[k4], x1 = h1[k4];
        int kb = k4 * 4;
#pragma unroll
        for (int kk = 0; kk < 4; kk++) {
            float2 wu = *(const float2*)&sm[(kb + kk) * 64 + c];
            float2 wv = *(const float2*)&sm[8192 + (kb + kk) * 64 + c];
            float v0 = ((const float*)&x0)[kk], v1 = ((const float*)&x1)[kk];
            au0x = fmaf(v0, wu.x, au0x); au0y = fmaf(v0, wu.y, au0y);
            au1x = fmaf(v1, wu.x, au1x); au1y = fmaf(v1, wu.y, au1y);
            av0x = fmaf(v0, wv.x, av0x); av0y = fmaf(v0, wv.y, av0y);
            av1x = fmaf(v1, wv.x, av1x); av1y = fmaf(v1, wv.y, av1y);
        }
    }
    *(float2*)&pu[(size_t)n0 * 64 + c] = make_float2(au0x, au0y);
    *(float2*)&pu[(size_t)n1 * 64 + c] = make_float2(au1x, au1y);
    *(float2*)&pv[(size_t)n0 * 64 + c] = make_float2(av0x, av0y);
    *(float2*)&pv[(size_t)n1 * 64 + c] = make_float2(av1x, av1y);
}

// ---------------- candidate kernel: gather+bias+leaky, 64x64 GEMM, final dot ----------------
// 64 candidates per block; 256 threads.
__global__ void k_cand(const float* __restrict__ pu, const float* __restrict__ pv,
                       const int* __restrict__ cu, const int* __restrict__ cv,
                       const float* __restrict__ cf,
                       const float* __restrict__ mw0, const float* __restrict__ mb0,
                       const float* __restrict__ mw1, const float* __restrict__ mb1,
                       const float* __restrict__ mw2, const float* __restrict__ mb2,
                       float* __restrict__ y, int C) {
    __shared__ float w1s[4096];     // 64x64
    __shared__ float z0s[64 * 68];  // 64 cands x 64 (stride 68)
    __shared__ float wfs[64], b0s[64], b1s[64], w2s[64];
    __shared__ float b2s;
    int tid = threadIdx.x;
    for (int i = tid; i < 4096; i += 256) w1s[i] = mw1[i];
    if (tid < 64) {
        wfs[tid] = mw0[256 * 64 + tid];
        b0s[tid] = mb0[tid];
        b1s[tid] = mb1[tid];
        w2s[tid] = mw2[tid];
    }
    if (tid == 0) b2s = mb2[0];
    __syncthreads();

    int base = blockIdx.x * 64;

    // phase A: z0 = leaky(Pu[u] + Pv[v] + f*wf + b0)
    {
        int jc = tid & 15, j = jc * 4;
        int c0 = tid >> 4;
#pragma unroll
        for (int i = 0; i < 4; i++) {
            int cl = c0 + 16 * i;
            int gc = base + cl;
            float4 z;
            if (gc < C) {
                int u = cu[gc], v = cv[gc];
                float f = cf[gc];
                float4 a = *(const float4*)&pu[(size_t)u * 64 + j];
                float4 b = *(const float4*)&pv[(size_t)v * 64 + j];
                float4 wf4 = *(const float4*)&wfs[j];
                float4 bb4 = *(const float4*)&b0s[j];
                z.x = a.x + b.x + f * wf4.x + bb4.x;
                z.y = a.y + b.y + f * wf4.y + bb4.y;
                z.z = a.z + b.z + f * wf4.z + bb4.z;
                z.w = a.w + b.w + f * wf4.w + bb4.w;
                z.x = z.x >= 0.f ? z.x : NEG * z.x;
                z.y = z.y >= 0.f ? z.y : NEG * z.y;
                z.z = z.z >= 0.f ? z.z : NEG * z.z;
                z.w = z.w >= 0.f ? z.w : NEG * z.w;
            } else {
                z = make_float4(0.f, 0.f, 0.f, 0.f);
            }
            *(float4*)&z0s[cl * 68 + j] = z;
        }
    }
    __syncthreads();

    // phase B: z1 = leaky(z0 @ w1 + b1); y = z1 @ w2 + b2
    {
        int oc = tid & 15, cg = tid >> 4;
        int ob = oc * 4;
        float acc0[4] = {0.f, 0.f, 0.f, 0.f};
        float acc1[4] = {0.f, 0.f, 0.f, 0.f};
        float acc2[4] = {0.f, 0.f, 0.f, 0.f};
        float acc3[4] = {0.f, 0.f, 0.f, 0.f};
        const float* z0 = &z0s[(cg * 4 + 0) * 68];
        const float* z1 = &z0s[(cg * 4 + 1) * 68];
        const float* z2 = &z0s[(cg * 4 + 2) * 68];
        const float* z3 = &z0s[(cg * 4 + 3) * 68];
#pragma unroll 8
        for (int k = 0; k < 64; k++) {
            float4 wv = *(const float4*)&w1s[k * 64 + ob];
            float q0 = z0[k], q1 = z1[k], q2 = z2[k], q3 = z3[k];
            acc0[0] = fmaf(q0, wv.x, acc0[0]); acc0[1] = fmaf(q0, wv.y, acc0[1]);
            acc0[2] = fmaf(q0, wv.z, acc0[2]); acc0[3] = fmaf(q0, wv.w, acc0[3]);
            acc1[0] = fmaf(q1, wv.x, acc1[0]); acc1[1] = fmaf(q1, wv.y, acc1[1]);
            acc1[2] = fmaf(q1, wv.z, acc1[2]); acc1[3] = fmaf(q1, wv.w, acc1[3]);
            acc2[0] = fmaf(q2, wv.x, acc2[0]); acc2[1] = fmaf(q2, wv.y, acc2[1]);
            acc2[2] = fmaf(q2, wv.z, acc2[2]); acc2[3] = fmaf(q2, wv.w, acc2[3]);
            acc3[0] = fmaf(q3, wv.x, acc3[0]); acc3[1] = fmaf(q3, wv.y, acc3[1]);
            acc3[2] = fmaf(q3, wv.z, acc3[2]); acc3[3] = fmaf(q3, wv.w, acc3[3]);
        }
        float4 bb = *(const float4*)&b1s[ob];
        float4 w2v = *(const float4*)&w2s[ob];
        float part[4];
        {
            float* accs[4] = {acc0, acc1, acc2, acc3};
#pragma unroll
            for (int q = 0; q < 4; q++) {
                float t0 = accs[q][0] + bb.x; t0 = t0 >= 0.f ? t0 : NEG * t0;
                float t1 = accs[q][1] + bb.y; t1 = t1 >= 0.f ? t1 : NEG * t1;
                float t2 = accs[q][2] + bb.z; t2 = t2 >= 0.f ? t2 : NEG * t2;
                float t3 = accs[q][3] + bb.w; t3 = t3 >= 0.f ? t3 : NEG * t3;
                part[q] = t0 * w2v.x + t1 * w2v.y + t2 * w2v.z + t3 * w2v.w;
            }
        }
#pragma unroll
        for (int q = 0; q < 4; q++) {
#pragma unroll
            for (int o = 8; o; o >>= 1)
                part[q] += __shfl_xor_sync(0xffffffffu, part[q], o);
        }
        if (oc == 0) {
#pragma unroll
            for (int q = 0; q < 4; q++) {
                int gc = base + cg * 4 + q;
                if (gc < C) y[gc] = part[q] + b2s;
            }
        }
    }
}

// ---------------- softmax over C (deterministic tree reductions) ----------------
__global__ void k_rmax(const float* __restrict__ y, int C) {
    __shared__ float sm[256];
    float m = -3.402823466e38f;
    for (int i = blockIdx.x * 256 + threadIdx.x; i < C; i += gridDim.x * 256)
        m = fmaxf(m, y[i]);
    sm[threadIdx.x] = m;
    __syncthreads();
    for (int s = 128; s; s >>= 1) {
        if (threadIdx.x < s) sm[threadIdx.x] = fmaxf(sm[threadIdx.x], sm[threadIdx.x + s]);
        __syncthreads();
    }
    if (threadIdx.x == 0) g_part[blockIdx.x] = sm[0];
}

__global__ void k_rmax_fin(int nb) {
    __shared__ float sm[256];
    float m = -3.402823466e38f;
    if (threadIdx.x < nb) m = g_part[threadIdx.x];
    sm[threadIdx.x] = m;
    __syncthreads();
    for (int s = 128; s; s >>= 1) {
        if (threadIdx.x < s) sm[threadIdx.x] = fmaxf(sm[threadIdx.x], sm[threadIdx.x + s]);
        __syncthreads();
    }
    if (threadIdx.x == 0) g_max_v = sm[0];
}

__global__ void k_rsum(const float* __restrict__ y, int C) {
    __shared__ float sm[256];
    float mx = g_max_v;
    float s = 0.f;
    for (int i = blockIdx.x * 256 + threadIdx.x; i < C; i += gridDim.x * 256)
        s += expf(y[i] - mx);
    sm[threadIdx.x] = s;
    __syncthreads();
    for (int st = 128; st; st >>= 1) {
        if (threadIdx.x < st) sm[threadIdx.x] += sm[threadIdx.x + st];
        __syncthreads();
    }
    if (threadIdx.x == 0) g_part[blockIdx.x] = sm[0];
}

__global__ void k_rsum_fin(int nb) {
    __shared__ float sm[256];
    float s = (threadIdx.x < nb) ? g_part[threadIdx.x] : 0.f;
    sm[threadIdx.x] = s;
    __syncthreads();
    for (int st = 128; st; st >>= 1) {
        if (threadIdx.x < st) sm[threadIdx.x] += sm[threadIdx.x + st];
        __syncthreads();
    }
    if (threadIdx.x == 0) g_sum_v = sm[0];
}

__global__ void k_soft(const float* __restrict__ y, float* __restrict__ out, int C) {
    float mx = g_max_v;
    float inv = 1.0f / g_sum_v;
    for (int i = blockIdx.x * 256 + threadIdx.x; i < C; i += gridDim.x * 256)
        out[i] = expf(y[i] - mx) * inv;
}

// ---------------- host launcher ----------------
extern "C" void kernel_launch(void* const* d_in, const int* in_sizes, int n_in,
                              void* d_out, int out_size) {
    const float* x   = (const float*)d_in[0];
    const int* src   = (const int*)d_in[1];
    const int* dst   = (const int*)d_in[2];
    const int* cu    = (const int*)d_in[3];
    const int* cv    = (const int*)d_in[4];
    const float* cf  = (const float*)d_in[5];
    const float* ws0 = (const float*)d_in[6];
    const float* wn0 = (const float*)d_in[7];
    const float* b0  = (const float*)d_in[8];
    const float* ga0 = (const float*)d_in[9];
    const float* be0 = (const float*)d_in[10];
    const float* rm0 = (const float*)d_in[11];
    const float* rv0 = (const float*)d_in[12];
    const float* ws1 = (const float*)d_in[13];
    const float* wn1 = (const float*)d_in[14];
    const float* b1  = (const float*)d_in[15];
    const float* ga1 = (const float*)d_in[16];
    const float* be1 = (const float*)d_in[17];
    const float* rm1 = (const float*)d_in[18];
    const float* rv1 = (const float*)d_in[19];
    const float* mw0 = (const float*)d_in[20];
    const float* mb0 = (const float*)d_in[21];
    const float* mw1 = (const float*)d_in[22];
    const float* mb1 = (const float*)d_in[23];
    const float* mw2 = (const float*)d_in[24];
    const float* mb2 = (const float*)d_in[25];

    int E = in_sizes[1];
    int C = in_sizes[3];
    float* y = (float*)d_out;
    float* soft = y + C;

    float *h0p, *h1p, *aggp, *pup, *pvp;
    cudaGetSymbolAddress((void**)&h0p, g_h0);
    cudaGetSymbolAddress((void**)&h1p, g_h1);
    cudaGetSymbolAddress((void**)&aggp, g_agg);
    cudaGetSymbolAddress((void**)&pup, g_pu);
    cudaGetSymbolAddress((void**)&pvp, g_pv);

    cudaFuncSetAttribute(k_gemm, cudaFuncAttributeMaxDynamicSharedMemorySize, 131072);
    cudaFuncSetAttribute(k_prep, cudaFuncAttributeMaxDynamicSharedMemorySize, 65536);

    const int NB_SCAN = (Nn + 1023) / 1024;  // 49

    // CSR build (reused by both layers)
    k_zero_deg<<<(Nn + 255) / 256, 256>>>();
    k_count<<<1024, 256>>>(dst, E);
    k_scan_partial<<<NB_SCAN, 1024>>>();
    k_scan_bsum<<<1, 32>>>(NB_SCAN);
    k_scan_add<<<NB_SCAN, 1024>>>();
    k_copy_cur<<<(Nn + 255) / 256, 256>>>();
    k_fill<<<1024, 256>>>(src, dst, E);

    // layer 0
    k_agg<<<(Nn + 7) / 8, 256>>>(x, aggp);
    k_gemm<<<(Nn + 15) / 16, 256, 131072>>>(x, aggp, ws0, wn0, b0, ga0, be0, rm0, rv0, h0p, 0);

    // layer 1 (+ nan_to_num fused)
    k_agg<<<(Nn + 7) / 8, 256>>>(h0p, aggp);
    k_gemm<<<(Nn + 15) / 16, 256, 131072>>>(h0p, aggp, ws1, wn1, b1, ga1, be1, rm1, rv1, h1p, 1);

    // MLP layer0 hoisted to node level
    k_prep<<<(Nn + 15) / 16, 256, 65536>>>(h1p, mw0, pup, pvp);

    // candidate tail (gather + layers 1,2) -> y
    k_cand<<<(C + 63) / 64, 256>>>(pup, pvp, cu, cv, cf, mw0, mb0, mw1, mb1, mw2, mb2, y, C);

    // softmax over C
    k_rmax<<<256, 256>>>(y, C);
    k_rmax_fin<<<1, 256>>>(256);
    k_rsum<<<256, 256>>>(y, C);
    k_rsum_fin<<<1, 256>>>(256);
    k_soft<<<256, 256>>>(y, soft, C);
}

// round 5
// speedup vs baseline: 1.3995x; 1.0865x over previous
#include <cuda_runtime.h>
#include <math.h>

#define Nn 50000
#define Ee 800000
#define Cc 100000
#define D 128
#define NEG 0.01f
#define BN_EPS 1e-5f

#define FMA2(d, a, b) asm("fma.rn.f32x2 %0, %1, %2, %0;" : "+l"(d) : "l"(a), "l"(b))
#define UNPACK2(lo, hi, v) asm("mov.b64 {%0, %1}, %2;" : "=f"(lo), "=f"(hi) : "l"(v))

// ---------------- scratch (static __device__, no allocation) ----------------
__device__ float g_h0[(size_t)Nn * D];
__device__ float g_h1[(size_t)Nn * D];
__device__ float g_pu[(size_t)Nn * 64];
__device__ float g_pv[(size_t)Nn * 64];
__device__ int   g_deg[Nn];
__device__ int   g_off[Nn + 1];
__device__ int   g_cur[Nn];
__device__ int   g_csr[Ee];
__device__ int   g_bsum[64];
__device__ float g_part[256];
__device__ float g_max_v;
__device__ float g_sum_v;

// ---------------- CSR build ----------------
__global__ void k_zero_deg() {
    int i = blockIdx.x * blockDim.x + threadIdx.x;
    if (i < Nn) g_deg[i] = 0;
}

__global__ void k_count(const int* __restrict__ dst, int E) {
    for (int e = blockIdx.x * blockDim.x + threadIdx.x; e < E; e += gridDim.x * blockDim.x)
        atomicAdd(&g_deg[dst[e]], 1);
}

// shfl-based block scan (1024 threads)
__global__ void k_scan_partial() {
    __shared__ int ws[32];
    int i = blockIdx.x * 1024 + threadIdx.x;
    int lane = threadIdx.x & 31, wid = threadIdx.x >> 5;
    int v = (i < Nn) ? g_deg[i] : 0;
    int s = v;
#pragma unroll
    for (int o = 1; o < 32; o <<= 1) {
        int t = __shfl_up_sync(0xffffffffu, s, o);
        if (lane >= o) s += t;
    }
    if (lane == 31) ws[wid] = s;
    __syncthreads();
    if (wid == 0) {
        int t = ws[lane];
#pragma unroll
        for (int o = 1; o < 32; o <<= 1) {
            int u = __shfl_up_sync(0xffffffffu, t, o);
            if (lane >= o) t += u;
        }
        ws[lane] = t;
    }
    __syncthreads();
    int off = wid ? ws[wid - 1] : 0;
    s += off;
    if (i < Nn) g_off[i + 1] = s;
    if (threadIdx.x == 1023) g_bsum[blockIdx.x] = s;
}

// exclusive scan of up to 64 block sums, one warp
__global__ void k_scan_bsum(int nb) {
    int lane = threadIdx.x;
    int a = (lane < nb) ? g_bsum[lane] : 0;
    int b = (lane + 32 < nb) ? g_bsum[lane + 32] : 0;
    int ia = a;
#pragma unroll
    for (int o = 1; o < 32; o <<= 1) {
        int t = __shfl_up_sync(0xffffffffu, ia, o);
        if (lane >= o) ia += t;
    }
    int tot = __shfl_sync(0xffffffffu, ia, 31);
    int ib = b;
#pragma unroll
    for (int o = 1; o < 32; o <<= 1) {
        int t = __shfl_up_sync(0xffffffffu, ib, o);
        if (lane >= o) ib += t;
    }
    ib += tot;
    if (lane < nb) g_bsum[lane] = ia - a;
    if (lane + 32 < nb) g_bsum[lane + 32] = ib - b;
}

// add block offsets; also produce g_cur (= g_off) for k_fill
__global__ void k_scan_add() {
    int i = blockIdx.x * 1024 + threadIdx.x;
    if (i < Nn) {
        int v = g_off[i + 1] + g_bsum[blockIdx.x];
        g_off[i + 1] = v;
        if (i + 1 < Nn) g_cur[i + 1] = v;
    }
    if (i == 0) { g_off[0] = 0; g_cur[0] = 0; }
}

__global__ void k_fill(const int* __restrict__ src, const int* __restrict__ dst, int E) {
    for (int e = blockIdx.x * blockDim.x + threadIdx.x; e < E; e += gridDim.x * blockDim.x) {
        int d = dst[e];
        int p = atomicAdd(&g_cur[d], 1);
        g_csr[p] = src[e];
    }
}

// ---------------- fused: segment-mean agg + dual GEMM + BN + leaky ----------------
// 32 nodes/block, 256 threads (8 warps x 4 nodes). f32x2 packed FMAs.
// smem: sW [32768 floats] (Ws then Wn), sSelfD [8192], sAggD [8192]  = 192KB
__global__ void k_fused(const float* __restrict__ A,
                        const float* __restrict__ Ws, const float* __restrict__ Wn,
                        const float* __restrict__ bias, const float* __restrict__ gamma,
                        const float* __restrict__ beta, const float* __restrict__ rm,
                        const float* __restrict__ rv, float* __restrict__ out, int fixnan) {
    extern __shared__ float sm[];
    float* sW = sm;                 // [0, 32768)
    float* sSelfD = sm + 32768;     // [32768, 40960)  32 nodes x 128 x 2 (duplicated)
    float* sAggD = sm + 40960;      // [40960, 49152)
    {
        float4* d0 = (float4*)sW;
        const float4* s0 = (const float4*)Ws;
        const float4* s1 = (const float4*)Wn;
        for (int i = threadIdx.x; i < 4096; i += 256) {
            d0[i] = s0[i];
            d0[4096 + i] = s1[i];
        }
    }
    __syncthreads();

    int w = threadIdx.x >> 5, l = threadIdx.x & 31;
    int nl0 = w * 4;
    int n0 = blockIdx.x * 32 + nl0;

    // phase A: gather-mean + self row, stored duplicated for b64 broadcast
#pragma unroll
    for (int t = 0; t < 4; t++) {
        int node = n0 + t;
        float4 xv = make_float4(0.f, 0.f, 0.f, 0.f);
        float4 ag = make_float4(0.f, 0.f, 0.f, 0.f);
        if (node < Nn) {
            xv = ((const float4*)(A + (size_t)node * D))[l];
            int s = g_off[node], e = g_off[node + 1];
            float4 a1 = make_float4(0.f, 0.f, 0.f, 0.f);
            float4 a2 = make_float4(0.f, 0.f, 0.f, 0.f);
            float4 a3 = make_float4(0.f, 0.f, 0.f, 0.f);
            int i = s;
            for (; i + 4 <= e; i += 4) {
                int s0 = g_csr[i], s1 = g_csr[i + 1], s2 = g_csr[i + 2], s3 = g_csr[i + 3];
                float4 v0 = ((const float4*)(A + (size_t)s0 * D))[l];
                float4 v1 = ((const float4*)(A + (size_t)s1 * D))[l];
                float4 v2 = ((const float4*)(A + (size_t)s2 * D))[l];
                float4 v3 = ((const float4*)(A + (size_t)s3 * D))[l];
                ag.x += v0.x; ag.y += v0.y; ag.z += v0.z; ag.w += v0.w;
                a1.x += v1.x; a1.y += v1.y; a1.z += v1.z; a1.w += v1.w;
                a2.x += v2.x; a2.y += v2.y; a2.z += v2.z; a2.w += v2.w;
                a3.x += v3.x; a3.y += v3.y; a3.z += v3.z; a3.w += v3.w;
            }
            for (; i < e; i++) {
                int sr = g_csr[i];
                float4 v = ((const float4*)(A + (size_t)sr * D))[l];
                ag.x += v.x; ag.y += v.y; ag.z += v.z; ag.w += v.w;
            }
            ag.x += a1.x + a2.x + a3.x;
            ag.y += a1.y + a2.y + a3.y;
            ag.z += a1.z + a2.z + a3.z;
            ag.w += a1.w + a2.w + a3.w;
            int deg = e - s;
            float inv = 1.0f / (float)(deg > 1 ? deg : 1);
            ag.x *= inv; ag.y *= inv; ag.z *= inv; ag.w *= inv;
        }
        float* sd = sSelfD + (nl0 + t) * 256 + l * 8;
        ((float4*)sd)[0] = make_float4(xv.x, xv.x, xv.y, xv.y);
        ((float4*)sd)[1] = make_float4(xv.z, xv.z, xv.w, xv.w);
        float* ad = sAggD + (nl0 + t) * 256 + l * 8;
        ((float4*)ad)[0] = make_float4(ag.x, ag.x, ag.y, ag.y);
        ((float4*)ad)[1] = make_float4(ag.z, ag.z, ag.w, ag.w);
    }
    __syncwarp();

    // phase B: h = x@Ws + agg@Wn using f32x2
    const float* wsb = sW + l * 4;
    const float* wnb = sW + 16384 + l * 4;
    const float* xr = sSelfD + nl0 * 256;
    const float* ar = sAggD + nl0 * 256;
    unsigned long long a01[4] = {0ull, 0ull, 0ull, 0ull};
    unsigned long long a23[4] = {0ull, 0ull, 0ull, 0ull};
#pragma unroll 8
    for (int k = 0; k < 128; k++) {
        ulonglong2 wsp = *(const ulonglong2*)(wsb + k * 128);
        ulonglong2 wnp = *(const ulonglong2*)(wnb + k * 128);
#pragma unroll
        for (int t = 0; t < 4; t++) {
            unsigned long long xv = *(const unsigned long long*)(xr + t * 256 + 2 * k);
            unsigned long long av = *(const unsigned long long*)(ar + t * 256 + 2 * k);
            FMA2(a01[t], xv, wsp.x);
            FMA2(a23[t], xv, wsp.y);
            FMA2(a01[t], av, wnp.x);
            FMA2(a23[t], av, wnp.y);
        }
    }

    // epilogue
    int c = l * 4;
    float4 bb = *(const float4*)&bias[c];
    float4 ga = *(const float4*)&gamma[c];
    float4 be = *(const float4*)&beta[c];
    float4 rmv = *(const float4*)&rm[c];
    float4 rvv = *(const float4*)&rv[c];
    float sc[4], sh[4];
    sc[0] = ga.x * rsqrtf(rvv.x + BN_EPS); sh[0] = be.x - rmv.x * sc[0];
    sc[1] = ga.y * rsqrtf(rvv.y + BN_EPS); sh[1] = be.y - rmv.y * sc[1];
    sc[2] = ga.z * rsqrtf(rvv.z + BN_EPS); sh[2] = be.z - rmv.z * sc[2];
    sc[3] = ga.w * rsqrtf(rvv.w + BN_EPS); sh[3] = be.w - rmv.w * sc[3];
    const float* bbp = (const float*)&bb;
#pragma unroll
    for (int t = 0; t < 4; t++) {
        int node = n0 + t;
        if (node >= Nn) continue;
        float o[4];
        UNPACK2(o[0], o[1], a01[t]);
        UNPACK2(o[2], o[3], a23[t]);
#pragma unroll
        for (int j = 0; j < 4; j++) {
            float v = o[j] + bbp[j];
            v = v * sc[j] + sh[j];
            v = v >= 0.f ? v : NEG * v;
            if (fixnan) {
                if (isnan(v)) v = 1e-14f;
                else if (isinf(v)) v = v > 0.f ? 3.402823466e38f : -3.402823466e38f;
            }
            o[j] = v;
        }
        *(float4*)&out[(size_t)node * D + c] = make_float4(o[0], o[1], o[2], o[3]);
    }
}

// ---------------- node-level MLP layer0 projection ----------------
__global__ void k_prep(const float* __restrict__ h, const float* __restrict__ mw0,
                       float* __restrict__ pu, float* __restrict__ pv) {
    extern __shared__ float sm[];  // 16384 floats
    {
        float4* d = (float4*)sm; const float4* s = (const float4*)mw0;
        for (int i = threadIdx.x; i < 4096; i += 256) d[i] = s[i];
    }
    __syncthreads();
    int w = threadIdx.x >> 5, l = threadIdx.x & 31;
    int n0 = blockIdx.x * 16 + w * 2;
    if (n0 >= Nn) return;
    int n1 = n0 + 1;
    float au0x = 0.f, au0y = 0.f, au1x = 0.f, au1y = 0.f;
    float av0x = 0.f, av0y = 0.f, av1x = 0.f, av1y = 0.f;
    const float4* h0 = (const float4*)(h + (size_t)n0 * D);
    const float4* h1 = (const float4*)(h + (size_t)n1 * D);
    int c = l * 2;
#pragma unroll 4
    for (int k4 = 0; k4 < 32; k4++) {
        float4 x0 = h0[k4], x1 = h1[k4];
        int kb = k4 * 4;
#pragma unroll
        for (int kk = 0; kk < 4; kk++) {
            float2 wu = *(const float2*)&sm[(kb + kk) * 64 + c];
            float2 wv = *(const float2*)&sm[8192 + (kb + kk) * 64 + c];
            float v0 = ((const float*)&x0)[kk], v1 = ((const float*)&x1)[kk];
            au0x = fmaf(v0, wu.x, au0x); au0y = fmaf(v0, wu.y, au0y);
            au1x = fmaf(v1, wu.x, au1x); au1y = fmaf(v1, wu.y, au1y);
            av0x = fmaf(v0, wv.x, av0x); av0y = fmaf(v0, wv.y, av0y);
            av1x = fmaf(v1, wv.x, av1x); av1y = fmaf(v1, wv.y, av1y);
        }
    }
    *(float2*)&pu[(size_t)n0 * 64 + c] = make_float2(au0x, au0y);
    *(float2*)&pu[(size_t)n1 * 64 + c] = make_float2(au1x, au1y);
    *(float2*)&pv[(size_t)n0 * 64 + c] = make_float2(av0x, av0y);
    *(float2*)&pv[(size_t)n1 * 64 + c] = make_float2(av1x, av1y);
}

// ---------------- candidate kernel ----------------
// 64 candidates/block; 256 threads. z0 staged duplicated for f32x2 phase B.
// dynamic smem layout (floats):
//   w1s:  [0, 4096)
//   z0sD: [4096, 4096 + 64*136) = [4096, 12800)
//   wfs:  [12800, 12864)  b0s: [12864, 12928)  b1s: [12928, 12992)  w2s: [12992, 13056)
//   b2s:  [13056]  (pad to 13060)
// total = 13060 floats = 52240 bytes (opt-in dynamic)
#define Z0STRIDE 136
#define CAND_SMEM_FLOATS 13060
__global__ void k_cand(const float* __restrict__ pu, const float* __restrict__ pv,
                       const int* __restrict__ cu, const int* __restrict__ cv,
                       const float* __restrict__ cf,
                       const float* __restrict__ mw0, const float* __restrict__ mb0,
                       const float* __restrict__ mw1, const float* __restrict__ mb1,
                       const float* __restrict__ mw2, const float* __restrict__ mb2,
                       float* __restrict__ y, int C) {
    extern __shared__ float smc[];
    float* w1s = smc;
    float* z0sD = smc + 4096;
    float* wfs = smc + 12800;
    float* b0s = smc + 12864;
    float* b1s = smc + 12928;
    float* w2s = smc + 12992;
    float* b2s = smc + 13056;
    int tid = threadIdx.x;
    for (int i = tid; i < 4096; i += 256) w1s[i] = mw1[i];
    if (tid < 64) {
        wfs[tid] = mw0[256 * 64 + tid];
        b0s[tid] = mb0[tid];
        b1s[tid] = mb1[tid];
        w2s[tid] = mw2[tid];
    }
    if (tid == 0) b2s[0] = mb2[0];
    __syncthreads();

    int base = blockIdx.x * 64;

    // phase A: z0 = leaky(Pu[u] + Pv[v] + f*wf + b0), stored duplicated
    {
        int jc = tid & 15, j = jc * 4;
        int c0 = tid >> 4;
#pragma unroll
        for (int i = 0; i < 4; i++) {
            int cl = c0 + 16 * i;
            int gc = base + cl;
            float4 z = make_float4(0.f, 0.f, 0.f, 0.f);
            if (gc < C) {
                int u = cu[gc], v = cv[gc];
                float f = cf[gc];
                float4 a = *(const float4*)&pu[(size_t)u * 64 + j];
                float4 b = *(const float4*)&pv[(size_t)v * 64 + j];
                float4 wf4 = *(const float4*)&wfs[j];
                float4 bb4 = *(const float4*)&b0s[j];
                z.x = a.x + b.x + f * wf4.x + bb4.x;
                z.y = a.y + b.y + f * wf4.y + bb4.y;
                z.z = a.z + b.z + f * wf4.z + bb4.z;
                z.w = a.w + b.w + f * wf4.w + bb4.w;
                z.x = z.x >= 0.f ? z.x : NEG * z.x;
                z.y = z.y >= 0.f ? z.y : NEG * z.y;
                z.z = z.z >= 0.f ? z.z : NEG * z.z;
                z.w = z.w >= 0.f ? z.w : NEG * z.w;
            }
            float* zd = &z0sD[cl * Z0STRIDE + 2 * j];
            ((float4*)zd)[0] = make_float4(z.x, z.x, z.y, z.y);
            ((float4*)zd)[1] = make_float4(z.z, z.z, z.w, z.w);
        }
    }
    __syncthreads();

    // phase B: z1 = leaky(z0 @ w1 + b1); y = z1 @ w2 + b2  (f32x2)
    {
        int oc = tid & 15, cg = tid >> 4;
        int ob = oc * 4;
        unsigned long long a01[4] = {0ull, 0ull, 0ull, 0ull};
        unsigned long long a23[4] = {0ull, 0ull, 0ull, 0ull};
        const float* z0 = &z0sD[(cg * 4 + 0) * Z0STRIDE];
        const float* z1 = &z0sD[(cg * 4 + 1) * Z0STRIDE];
        const float* z2 = &z0sD[(cg * 4 + 2) * Z0STRIDE];
        const float* z3 = &z0sD[(cg * 4 + 3) * Z0STRIDE];
#pragma unroll 8
        for (int k = 0; k < 64; k++) {
            ulonglong2 wp = *(const ulonglong2*)&w1s[k * 64 + ob];
            unsigned long long q0 = *(const unsigned long long*)(z0 + 2 * k);
            unsigned long long q1 = *(const unsigned long long*)(z1 + 2 * k);
            unsigned long long q2 = *(const unsigned long long*)(z2 + 2 * k);
            unsigned long long q3 = *(const unsigned long long*)(z3 + 2 * k);
            FMA2(a01[0], q0, wp.x); FMA2(a23[0], q0, wp.y);
            FMA2(a01[1], q1, wp.x); FMA2(a23[1], q1, wp.y);
            FMA2(a01[2], q2, wp.x); FMA2(a23[2], q2, wp.y);
            FMA2(a01[3], q3, wp.x); FMA2(a23[3], q3, wp.y);
        }
        float4 bb = *(const float4*)&b1s[ob];
        float4 w2v = *(const float4*)&w2s[ob];
        float part[4];
#pragma unroll
        for (int q = 0; q < 4; q++) {
            float t0, t1, t2, t3;
            UNPACK2(t0, t1, a01[q]);
            UNPACK2(t2, t3, a23[q]);
            t0 += bb.x; t0 = t0 >= 0.f ? t0 : NEG * t0;
            t1 += bb.y; t1 = t1 >= 0.f ? t1 : NEG * t1;
            t2 += bb.z; t2 = t2 >= 0.f ? t2 : NEG * t2;
            t3 += bb.w; t3 = t3 >= 0.f ? t3 : NEG * t3;
            part[q] = t0 * w2v.x + t1 * w2v.y + t2 * w2v.z + t3 * w2v.w;
        }
#pragma unroll
        for (int q = 0; q < 4; q++) {
#pragma unroll
            for (int o = 8; o; o >>= 1)
                part[q] += __shfl_xor_sync(0xffffffffu, part[q], o);
        }
        if (oc == 0) {
#pragma unroll
            for (int q = 0; q < 4; q++) {
                int gc = base + cg * 4 + q;
                if (gc < C) y[gc] = part[q] + b2s[0];
            }
        }
    }
}

// ---------------- softmax (3 kernels, deterministic) ----------------
__global__ void k_softA(const float* __restrict__ y, int C) {
    __shared__ float mm[256], ss[256];
    float m = -3.402823466e38f, s = 0.f;
    for (int i = blockIdx.x * 256 + threadIdx.x; i < C; i += gridDim.x * 256) {
        float v = y[i];
        if (v > m) { s = s * expf(m - v) + 1.0f; m = v; }
        else s += expf(v - m);
    }
    mm[threadIdx.x] = m; ss[threadIdx.x] = s;
    __syncthreads();
    for (int st = 128; st; st >>= 1) {
        if (threadIdx.x < st) {
            float m2 = mm[threadIdx.x + st], s2 = ss[threadIdx.x + st];
            float M = fmaxf(mm[threadIdx.x], m2);
            ss[threadIdx.x] = ss[threadIdx.x] * expf(mm[threadIdx.x] - M) + s2 * expf(m2 - M);
            mm[threadIdx.x] = M;
        }
        __syncthreads();
    }
    if (threadIdx.x == 0) { g_part[blockIdx.x] = mm[0]; g_part[128 + blockIdx.x] = ss[0]; }
}

__global__ void k_softB(int nb) {
    __shared__ float mm[128], ss[128];
    int t = threadIdx.x;
    mm[t] = (t < nb) ? g_part[t] : -3.402823466e38f;
    ss[t] = (t < nb) ? g_part[128 + t] : 0.f;
    __syncthreads();
    for (int st = 64; st; st >>= 1) {
        if (t < st) {
            float m2 = mm[t + st], s2 = ss[t + st];
            float M = fmaxf(mm[t], m2);
            ss[t] = ss[t] * expf(mm[t] - M) + s2 * expf(m2 - M);
            mm[t] = M;
        }
        __syncthreads();
    }
    if (t == 0) { g_max_v = mm[0]; g_sum_v = ss[0]; }
}

__global__ void k_soft(const float* __restrict__ y, float* __restrict__ out, int C) {
    float mx = g_max_v;
    float inv = 1.0f / g_sum_v;
    for (int i = blockIdx.x * 256 + threadIdx.x; i < C; i += gridDim.x * 256)
        out[i] = expf(y[i] - mx) * inv;
}

// ---------------- host launcher ----------------
extern "C" void kernel_launch(void* const* d_in, const int* in_sizes, int n_in,
                              void* d_out, int out_size) {
    const float* x   = (const float*)d_in[0];
    const int* src   = (const int*)d_in[1];
    const int* dst   = (const int*)d_in[2];
    const int* cu    = (const int*)d_in[3];
    const int* cv    = (const int*)d_in[4];
    const float* cf  = (const float*)d_in[5];
    const float* ws0 = (const float*)d_in[6];
    const float* wn0 = (const float*)d_in[7];
    const float* b0  = (const float*)d_in[8];
    const float* ga0 = (const float*)d_in[9];
    const float* be0 = (const float*)d_in[10];
    const float* rm0 = (const float*)d_in[11];
    const float* rv0 = (const float*)d_in[12];
    const float* ws1 = (const float*)d_in[13];
    const float* wn1 = (const float*)d_in[14];
    const float* b1  = (const float*)d_in[15];
    const float* ga1 = (const float*)d_in[16];
    const float* be1 = (const float*)d_in[17];
    const float* rm1 = (const float*)d_in[18];
    const float* rv1 = (const float*)d_in[19];
    const float* mw0 = (const float*)d_in[20];
    const float* mb0 = (const float*)d_in[21];
    const float* mw1 = (const float*)d_in[22];
    const float* mb1 = (const float*)d_in[23];
    const float* mw2 = (const float*)d_in[24];
    const float* mb2 = (const float*)d_in[25];

    int E = in_sizes[1];
    int C = in_sizes[3];
    float* y = (float*)d_out;
    float* soft = y + C;

    float *h0p, *h1p, *pup, *pvp;
    cudaGetSymbolAddress((void**)&h0p, g_h0);
    cudaGetSymbolAddress((void**)&h1p, g_h1);
    cudaGetSymbolAddress((void**)&pup, g_pu);
    cudaGetSymbolAddress((void**)&pvp, g_pv);

    cudaFuncSetAttribute(k_fused, cudaFuncAttributeMaxDynamicSharedMemorySize, 196608);
    cudaFuncSetAttribute(k_prep, cudaFuncAttributeMaxDynamicSharedMemorySize, 65536);
    cudaFuncSetAttribute(k_cand, cudaFuncAttributeMaxDynamicSharedMemorySize, CAND_SMEM_FLOATS * 4);

    const int NB_SCAN = (Nn + 1023) / 1024;  // 49

    // CSR build (reused by both layers)
    k_zero_deg<<<(Nn + 255) / 256, 256>>>();
    k_count<<<1024, 256>>>(dst, E);
    k_scan_partial<<<NB_SCAN, 1024>>>();
    k_scan_bsum<<<1, 32>>>(NB_SCAN);
    k_scan_add<<<NB_SCAN, 1024>>>();
    k_fill<<<1024, 256>>>(src, dst, E);

    // layer 0 (agg + gemm fused)
    k_fused<<<(Nn + 31) / 32, 256, 196608>>>(x, ws0, wn0, b0, ga0, be0, rm0, rv0, h0p, 0);

    // layer 1 (+ nan_to_num)
    k_fused<<<(Nn + 31) / 32, 256, 196608>>>(h0p, ws1, wn1, b1, ga1, be1, rm1, rv1, h1p, 1);

    // MLP layer0 hoisted to node level
    k_prep<<<(Nn + 15) / 16, 256, 65536>>>(h1p, mw0, pup, pvp);

    // candidate tail -> y
    k_cand<<<(C + 63) / 64, 256, CAND_SMEM_FLOATS * 4>>>(pup, pvp, cu, cv, cf, mw0, mb0, mw1, mb1, mw2, mb2, y, C);

    // softmax over C
    k_softA<<<128, 256>>>(y, C);
    k_softB<<<1, 128>>>(128);
    k_soft<<<256, 256>>>(y, soft, C);
}

// round 6
// speedup vs baseline: 1.4903x; 1.0649x over previous
#include <cuda_runtime.h>
#include <math.h>

#define Nn 50000
#define Ee 800000
#define Cc 100000
#define D 128
#define NEG 0.01f
#define BN_EPS 1e-5f
#define NB_SCAN 49

#define FMA2(d, a, b) asm("fma.rn.f32x2 %0, %1, %2, %0;" : "+l"(d) : "l"(a), "l"(b))
#define UNPACK2(lo, hi, v) asm("mov.b64 {%0, %1}, %2;" : "=f"(lo), "=f"(hi) : "l"(v))

// ---------------- scratch (static __device__, no allocation) ----------------
__device__ float g_h0[(size_t)Nn * D];
__device__ float g_h1[(size_t)Nn * D];
__device__ float g_pu[(size_t)Nn * 64];
__device__ float g_pv[(size_t)Nn * 64];
__device__ int   g_deg[Nn];
__device__ int   g_off[Nn + 1];
__device__ int   g_cur[Nn];
__device__ int   g_csr[Ee];
__device__ unsigned long long g_lb[NB_SCAN];  // lookback: (aggregate<<1)|1
__device__ unsigned int g_done;
__device__ float g_part[256];

// ---------------- zero state ----------------
__global__ void k_zero() {
    int i = blockIdx.x * blockDim.x + threadIdx.x;
    if (i < Nn) g_deg[i] = 0;
    if (i < NB_SCAN) g_lb[i] = 0ull;
    if (i == 0) g_done = 0u;
}

__global__ void k_count(const int* __restrict__ dst, int E) {
    for (int e = blockIdx.x * blockDim.x + threadIdx.x; e < E; e += gridDim.x * blockDim.x)
        atomicAdd(&g_deg[dst[e]], 1);
}

// ---------------- single-pass: scan (lookback) + grid barrier + CSR fill ----------------
// launched with exactly NB_SCAN blocks x 1024 threads (all co-resident).
__global__ void k_scanfill(const int* __restrict__ src, const int* __restrict__ dst, int E) {
    __shared__ int ws[32];
    __shared__ int preds[64];
    __shared__ int sbase;
    int b = blockIdx.x;
    int tid = threadIdx.x;
    int i = b * 1024 + tid;
    int lane = tid & 31, wid = tid >> 5;
    int v = (i < Nn) ? g_deg[i] : 0;
    int s = v;
#pragma unroll
    for (int o = 1; o < 32; o <<= 1) {
        int t = __shfl_up_sync(0xffffffffu, s, o);
        if (lane >= o) s += t;
    }
    if (lane == 31) ws[wid] = s;
    __syncthreads();
    if (wid == 0) {
        int t = ws[lane];
#pragma unroll
        for (int o = 1; o < 32; o <<= 1) {
            int u = __shfl_up_sync(0xffffffffu, t, o);
            if (lane >= o) t += u;
        }
        ws[lane] = t;
    }
    __syncthreads();
    s += wid ? ws[wid - 1] : 0;  // local inclusive

    // publish this block's aggregate
    if (tid == 1023)
        atomicExch(&g_lb[b], (((unsigned long long)(unsigned)s) << 1) | 1ull);

    // gather predecessors' aggregates
    if (tid < b) {
        unsigned long long x;
        do { x = atomicAdd(&g_lb[tid], 0ull); } while (!(x & 1ull));
        preds[tid] = (int)(x >> 1);
    }
    __syncthreads();
    if (tid == 0) {
        int acc = 0;
        for (int j = 0; j < b; j++) acc += preds[j];
        sbase = acc;
    }
    __syncthreads();
    s += sbase;

    if (i < Nn) {
        g_off[i + 1] = s;
        g_cur[i] = s - v;  // exclusive prefix
    }
    if (i == 0) g_off[0] = 0;

    // grid barrier
    __threadfence();
    __syncthreads();
    if (tid == 0) {
        atomicAdd(&g_done, 1u);
        while (atomicAdd(&g_done, 0u) < (unsigned)gridDim.x) {}
    }
    __syncthreads();

    // fill phase
    int stride = gridDim.x * 1024;
    for (int e = b * 1024 + tid; e < E; e += stride) {
        int d = dst[e];
        int p = atomicAdd(&g_cur[d], 1);
        g_csr[p] = src[e];
    }
}

// ---------------- fused: segment-mean agg + dual GEMM + BN + leaky ----------------
// 32 nodes/block, 256 threads (8 warps x 4 nodes). f32x2 packed FMAs.
// smem: sWs[16384], sWn[16384], sVal[32 nodes x 128 k x 4 (x,x,a,a)] = 16384  -> 192KB
__global__ void k_fused(const float* __restrict__ A,
                        const float* __restrict__ Ws, const float* __restrict__ Wn,
                        const float* __restrict__ bias, const float* __restrict__ gamma,
                        const float* __restrict__ beta, const float* __restrict__ rm,
                        const float* __restrict__ rv, float* __restrict__ out, int fixnan) {
    extern __shared__ float sm[];
    float* sWs = sm;                // [0, 16384)
    float* sWn = sm + 16384;        // [16384, 32768)
    float* sVal = sm + 32768;       // [32768, 49152)  node stride 512 floats
    {
        float4* d0 = (float4*)sWs; const float4* s0 = (const float4*)Ws;
        float4* d1 = (float4*)sWn; const float4* s1 = (const float4*)Wn;
        for (int i = threadIdx.x; i < 4096; i += 256) { d0[i] = s0[i]; d1[i] = s1[i]; }
    }
    __syncthreads();

    int w = threadIdx.x >> 5, l = threadIdx.x & 31;
    int nl0 = w * 4;
    int n0 = blockIdx.x * 32 + nl0;

    // phase A: gather-mean + self row, stored (x,x,a,a) per k
#pragma unroll
    for (int t = 0; t < 4; t++) {
        int node = n0 + t;
        float4 xv = make_float4(0.f, 0.f, 0.f, 0.f);
        float4 ag = make_float4(0.f, 0.f, 0.f, 0.f);
        if (node < Nn) {
            xv = ((const float4*)(A + (size_t)node * D))[l];
            int s = g_off[node], e = g_off[node + 1];
            float4 a1 = make_float4(0.f, 0.f, 0.f, 0.f);
            float4 a2 = make_float4(0.f, 0.f, 0.f, 0.f);
            float4 a3 = make_float4(0.f, 0.f, 0.f, 0.f);
            int i = s;
            for (; i + 4 <= e; i += 4) {
                int s0 = g_csr[i], s1 = g_csr[i + 1], s2 = g_csr[i + 2], s3 = g_csr[i + 3];
                float4 v0 = ((const float4*)(A + (size_t)s0 * D))[l];
                float4 v1 = ((const float4*)(A + (size_t)s1 * D))[l];
                float4 v2 = ((const float4*)(A + (size_t)s2 * D))[l];
                float4 v3 = ((const float4*)(A + (size_t)s3 * D))[l];
                ag.x += v0.x; ag.y += v0.y; ag.z += v0.z; ag.w += v0.w;
                a1.x += v1.x; a1.y += v1.y; a1.z += v1.z; a1.w += v1.w;
                a2.x += v2.x; a2.y += v2.y; a2.z += v2.z; a2.w += v2.w;
                a3.x += v3.x; a3.y += v3.y; a3.z += v3.z; a3.w += v3.w;
            }
            for (; i < e; i++) {
                int sr = g_csr[i];
                float4 vv = ((const float4*)(A + (size_t)sr * D))[l];
                ag.x += vv.x; ag.y += vv.y; ag.z += vv.z; ag.w += vv.w;
            }
            ag.x += a1.x + a2.x + a3.x;
            ag.y += a1.y + a2.y + a3.y;
            ag.z += a1.z + a2.z + a3.z;
            ag.w += a1.w + a2.w + a3.w;
            int deg = e - s;
            float inv = 1.0f / (float)(deg > 1 ? deg : 1);
            ag.x *= inv; ag.y *= inv; ag.z *= inv; ag.w *= inv;
        }
        // k = l*4 .. l*4+3; entry (node,k) at sVal[node*512 + k*4]
        float4* sd = (float4*)(sVal + (nl0 + t) * 512 + l * 16);
        sd[0] = make_float4(xv.x, xv.x, ag.x, ag.x);
        sd[1] = make_float4(xv.y, xv.y, ag.y, ag.y);
        sd[2] = make_float4(xv.z, xv.z, ag.z, ag.z);
        sd[3] = make_float4(xv.w, xv.w, ag.w, ag.w);
    }
    __syncwarp();

    // phase B: h = x@Ws + agg@Wn using f32x2; thread: 4 nodes x 4 cols
    int c = l * 4;
    const float* wsb = sWs + c;
    const float* wnb = sWn + c;
    const float* vb = sVal + nl0 * 512;
    unsigned long long a01[4] = {0ull, 0ull, 0ull, 0ull};
    unsigned long long a23[4] = {0ull, 0ull, 0ull, 0ull};
#pragma unroll 8
    for (int k = 0; k < 128; k++) {
        ulonglong2 wsp = *(const ulonglong2*)(wsb + k * 128);
        ulonglong2 wnp = *(const ulonglong2*)(wnb + k * 128);
#pragma unroll
        for (int t = 0; t < 4; t++) {
            ulonglong2 va = *(const ulonglong2*)(vb + t * 512 + k * 4);  // (x,x),(a,a)
            FMA2(a01[t], va.x, wsp.x);
            FMA2(a23[t], va.x, wsp.y);
            FMA2(a01[t], va.y, wnp.x);
            FMA2(a23[t], va.y, wnp.y);
        }
    }

    // epilogue
    float4 bb = *(const float4*)&bias[c];
    float4 ga = *(const float4*)&gamma[c];
    float4 be = *(const float4*)&beta[c];
    float4 rmv = *(const float4*)&rm[c];
    float4 rvv = *(const float4*)&rv[c];
    float sc[4], sh[4];
    sc[0] = ga.x * rsqrtf(rvv.x + BN_EPS); sh[0] = be.x - rmv.x * sc[0];
    sc[1] = ga.y * rsqrtf(rvv.y + BN_EPS); sh[1] = be.y - rmv.y * sc[1];
    sc[2] = ga.z * rsqrtf(rvv.z + BN_EPS); sh[2] = be.z - rmv.z * sc[2];
    sc[3] = ga.w * rsqrtf(rvv.w + BN_EPS); sh[3] = be.w - rmv.w * sc[3];
    const float* bbp = (const float*)&bb;
#pragma unroll
    for (int t = 0; t < 4; t++) {
        int node = n0 + t;
        if (node >= Nn) continue;
        float o[4];
        UNPACK2(o[0], o[1], a01[t]);
        UNPACK2(o[2], o[3], a23[t]);
#pragma unroll
        for (int j = 0; j < 4; j++) {
            float vv = o[j] + bbp[j];
            vv = vv * sc[j] + sh[j];
            vv = vv >= 0.f ? vv : NEG * vv;
            if (fixnan) {
                if (isnan(vv)) vv = 1e-14f;
                else if (isinf(vv)) vv = vv > 0.f ? 3.402823466e38f : -3.402823466e38f;
            }
            o[j] = vv;
        }
        *(float4*)&out[(size_t)node * D + c] = make_float4(o[0], o[1], o[2], o[3]);
    }
}

// ---------------- node-level MLP layer0 projection (f32x2) ----------------
// 32 nodes/block (8 warps x 4 nodes); lane l -> cols (2l, 2l+1).
// smem: sWI[128k x 32p x 4] = 16384 floats (interleaved wu0,wu1,wv0,wv1),
//       sVal[32 nodes x 128 k x 2 dup] = 8192 floats.  total 96KB
__global__ void k_prep(const float* __restrict__ h, const float* __restrict__ mw0,
                       float* __restrict__ pu, float* __restrict__ pv) {
    extern __shared__ float sm[];
    float* sWI = sm;            // [0, 16384)
    float* sVal = sm + 16384;   // [16384, 24576)  node stride 256
    // interleaved weight load: entry (k,p) -> {mw0[k][2p], mw0[k][2p+1], mw0[128+k][2p], mw0[128+k][2p+1]}
    for (int idx = threadIdx.x; idx < 4096; idx += 256) {
        int k = idx >> 5, p = idx & 31;
        float2 u = *(const float2*)&mw0[k * 64 + 2 * p];
        float2 v = *(const float2*)&mw0[(128 + k) * 64 + 2 * p];
        *(float4*)&sWI[k * 128 + p * 4] = make_float4(u.x, u.y, v.x, v.y);
    }
    __syncthreads();

    int w = threadIdx.x >> 5, l = threadIdx.x & 31;
    int nl0 = w * 4;
    int n0 = blockIdx.x * 32 + nl0;

    // stage h rows duplicated
#pragma unroll
    for (int t = 0; t < 4; t++) {
        int node = n0 + t;
        float4 xv = make_float4(0.f, 0.f, 0.f, 0.f);
        if (node < Nn) xv = ((const float4*)(h + (size_t)node * D))[l];
        float4* sd = (float4*)(sVal + (nl0 + t) * 256 + l * 8);
        sd[0] = make_float4(xv.x, xv.x, xv.y, xv.y);
        sd[1] = make_float4(xv.z, xv.z, xv.w, xv.w);
    }
    __syncwarp();

    unsigned long long au[4] = {0ull, 0ull, 0ull, 0ull};
    unsigned long long av[4] = {0ull, 0ull, 0ull, 0ull};
    const float* wib = sWI + l * 4;
    const float* vb = sVal + nl0 * 256;
#pragma unroll 8
    for (int k = 0; k < 128; k++) {
        ulonglong2 wp = *(const ulonglong2*)(wib + k * 128);  // (wu pair, wv pair)
#pragma unroll
        for (int t = 0; t < 4; t++) {
            unsigned long long xd = *(const unsigned long long*)(vb + t * 256 + 2 * k);
            FMA2(au[t], xd, wp.x);
            FMA2(av[t], xd, wp.y);
        }
    }
#pragma unroll
    for (int t = 0; t < 4; t++) {
        int node = n0 + t;
        if (node >= Nn) continue;
        *(float2*)&pu[(size_t)node * 64 + 2 * l] = *(float2*)&au[t];
        *(float2*)&pv[(size_t)node * 64 + 2 * l] = *(float2*)&av[t];
    }
}

// ---------------- candidate kernel ----------------
#define Z0STRIDE 136
#define CAND_SMEM_FLOATS 13060
__global__ void k_cand(const float* __restrict__ pu, const float* __restrict__ pv,
                       const int* __restrict__ cu, const int* __restrict__ cv,
                       const float* __restrict__ cf,
                       const float* __restrict__ mw0, const float* __restrict__ mb0,
                       const float* __restrict__ mw1, const float* __restrict__ mb1,
                       const float* __restrict__ mw2, const float* __restrict__ mb2,
                       float* __restrict__ y, int C) {
    extern __shared__ float smc[];
    float* w1s = smc;
    float* z0sD = smc + 4096;
    float* wfs = smc + 12800;
    float* b0s = smc + 12864;
    float* b1s = smc + 12928;
    float* w2s = smc + 12992;
    float* b2s = smc + 13056;
    int tid = threadIdx.x;
    for (int i = tid; i < 4096; i += 256) w1s[i] = mw1[i];
    if (tid < 64) {
        wfs[tid] = mw0[256 * 64 + tid];
        b0s[tid] = mb0[tid];
        b1s[tid] = mb1[tid];
        w2s[tid] = mw2[tid];
    }
    if (tid == 0) b2s[0] = mb2[0];
    __syncthreads();

    int base = blockIdx.x * 64;

    {
        int jc = tid & 15, j = jc * 4;
        int c0 = tid >> 4;
#pragma unroll
        for (int i = 0; i < 4; i++) {
            int cl = c0 + 16 * i;
            int gc = base + cl;
            float4 z = make_float4(0.f, 0.f, 0.f, 0.f);
            if (gc < C) {
                int u = cu[gc], v = cv[gc];
                float f = cf[gc];
                float4 a = *(const float4*)&pu[(size_t)u * 64 + j];
                float4 b = *(const float4*)&pv[(size_t)v * 64 + j];
                float4 wf4 = *(const float4*)&wfs[j];
                float4 bb4 = *(const float4*)&b0s[j];
                z.x = a.x + b.x + f * wf4.x + bb4.x;
                z.y = a.y + b.y + f * wf4.y + bb4.y;
                z.z = a.z + b.z + f * wf4.z + bb4.z;
                z.w = a.w + b.w + f * wf4.w + bb4.w;
                z.x = z.x >= 0.f ? z.x : NEG * z.x;
                z.y = z.y >= 0.f ? z.y : NEG * z.y;
                z.z = z.z >= 0.f ? z.z : NEG * z.z;
                z.w = z.w >= 0.f ? z.w : NEG * z.w;
            }
            float* zd = &z0sD[cl * Z0STRIDE + 2 * j];
            ((float4*)zd)[0] = make_float4(z.x, z.x, z.y, z.y);
            ((float4*)zd)[1] = make_float4(z.z, z.z, z.w, z.w);
        }
    }
    __syncthreads();

    {
        int oc = tid & 15, cg = tid >> 4;
        int ob = oc * 4;
        unsigned long long a01[4] = {0ull, 0ull, 0ull, 0ull};
        unsigned long long a23[4] = {0ull, 0ull, 0ull, 0ull};
        const float* z0 = &z0sD[(cg * 4 + 0) * Z0STRIDE];
        const float* z1 = &z0sD[(cg * 4 + 1) * Z0STRIDE];
        const float* z2 = &z0sD[(cg * 4 + 2) * Z0STRIDE];
        const float* z3 = &z0sD[(cg * 4 + 3) * Z0STRIDE];
#pragma unroll 8
        for (int k = 0; k < 64; k++) {
            ulonglong2 wp = *(const ulonglong2*)&w1s[k * 64 + ob];
            unsigned long long q0 = *(const unsigned long long*)(z0 + 2 * k);
            unsigned long long q1 = *(const unsigned long long*)(z1 + 2 * k);
            unsigned long long q2 = *(const unsigned long long*)(z2 + 2 * k);
            unsigned long long q3 = *(const unsigned long long*)(z3 + 2 * k);
            FMA2(a01[0], q0, wp.x); FMA2(a23[0], q0, wp.y);
            FMA2(a01[1], q1, wp.x); FMA2(a23[1], q1, wp.y);
            FMA2(a01[2], q2, wp.x); FMA2(a23[2], q2, wp.y);
            FMA2(a01[3], q3, wp.x); FMA2(a23[3], q3, wp.y);
        }
        float4 bb = *(const float4*)&b1s[ob];
        float4 w2v = *(const float4*)&w2s[ob];
        float part[4];
#pragma unroll
        for (int q = 0; q < 4; q++) {
            float t0, t1, t2, t3;
            UNPACK2(t0, t1, a01[q]);
            UNPACK2(t2, t3, a23[q]);
            t0 += bb.x; t0 = t0 >= 0.f ? t0 : NEG * t0;
            t1 += bb.y; t1 = t1 >= 0.f ? t1 : NEG * t1;
            t2 += bb.z; t2 = t2 >= 0.f ? t2 : NEG * t2;
            t3 += bb.w; t3 = t3 >= 0.f ? t3 : NEG * t3;
            part[q] = t0 * w2v.x + t1 * w2v.y + t2 * w2v.z + t3 * w2v.w;
        }
#pragma unroll
        for (int q = 0; q < 4; q++) {
#pragma unroll
            for (int o = 8; o; o >>= 1)
                part[q] += __shfl_xor_sync(0xffffffffu, part[q], o);
        }
        if (oc == 0) {
#pragma unroll
            for (int q = 0; q < 4; q++) {
                int gc = base + cg * 4 + q;
                if (gc < C) y[gc] = part[q] + b2s[0];
            }
        }
    }
}

// ---------------- softmax (2 kernels, deterministic) ----------------
__global__ void k_softA(const float* __restrict__ y, int C) {
    __shared__ float mm[256], ss[256];
    float m = -3.402823466e38f, s = 0.f;
    for (int i = blockIdx.x * 256 + threadIdx.x; i < C; i += gridDim.x * 256) {
        float v = y[i];
        if (v > m) { s = s * expf(m - v) + 1.0f; m = v; }
        else s += expf(v - m);
    }
    mm[threadIdx.x] = m; ss[threadIdx.x] = s;
    __syncthreads();
    for (int st = 128; st; st >>= 1) {
        if (threadIdx.x < st) {
            float m2 = mm[threadIdx.x + st], s2 = ss[threadIdx.x + st];
            float M = fmaxf(mm[threadIdx.x], m2);
            ss[threadIdx.x] = ss[threadIdx.x] * expf(mm[threadIdx.x] - M) + s2 * expf(m2 - M);
            mm[threadIdx.x] = M;
        }
        __syncthreads();
    }
    if (threadIdx.x == 0) { g_part[blockIdx.x] = mm[0]; g_part[128 + blockIdx.x] = ss[0]; }
}

// each block redundantly reduces the 128 partials, then writes its slice
__global__ void k_softFin(const float* __restrict__ y, float* __restrict__ out, int C) {
    __shared__ float mm[128], ss[128];
    int t = threadIdx.x;
    if (t < 128) { mm[t] = g_part[t]; ss[t] = g_part[128 + t]; }
    __syncthreads();
    for (int st = 64; st; st >>= 1) {
        if (t < st) {
            float m2 = mm[t + st], s2 = ss[t + st];
            float M = fmaxf(mm[t], m2);
            ss[t] = ss[t] * expf(mm[t] - M) + s2 * expf(m2 - M);
            mm[t] = M;
        }
        __syncthreads();
    }
    float mx = mm[0];
    float inv = 1.0f / ss[0];
    for (int i = blockIdx.x * 256 + t; i < C; i += gridDim.x * 256)
        out[i] = expf(y[i] - mx) * inv;
}

// ---------------- host launcher ----------------
extern "C" void kernel_launch(void* const* d_in, const int* in_sizes, int n_in,
                              void* d_out, int out_size) {
    const float* x   = (const float*)d_in[0];
    const int* src   = (const int*)d_in[1];
    const int* dst   = (const int*)d_in[2];
    const int* cu    = (const int*)d_in[3];
    const int* cv    = (const int*)d_in[4];
    const float* cf  = (const float*)d_in[5];
    const float* ws0 = (const float*)d_in[6];
    const float* wn0 = (const float*)d_in[7];
    const float* b0  = (const float*)d_in[8];
    const float* ga0 = (const float*)d_in[9];
    const float* be0 = (const float*)d_in[10];
    const float* rm0 = (const float*)d_in[11];
    const float* rv0 = (const float*)d_in[12];
    const float* ws1 = (const float*)d_in[13];
    const float* wn1 = (const float*)d_in[14];
    const float* b1  = (const float*)d_in[15];
    const float* ga1 = (const float*)d_in[16];
    const float* be1 = (const float*)d_in[17];
    const float* rm1 = (const float*)d_in[18];
    const float* rv1 = (const float*)d_in[19];
    const float* mw0 = (const float*)d_in[20];
    const float* mb0 = (const float*)d_in[21];
    const float* mw1 = (const float*)d_in[22];
    const float* mb1 = (const float*)d_in[23];
    const float* mw2 = (const float*)d_in[24];
    const float* mb2 = (const float*)d_in[25];

    int E = in_sizes[1];
    int C = in_sizes[3];
    float* y = (float*)d_out;
    float* soft = y + C;

    float *h0p, *h1p, *pup, *pvp;
    cudaGetSymbolAddress((void**)&h0p, g_h0);
    cudaGetSymbolAddress((void**)&h1p, g_h1);
    cudaGetSymbolAddress((void**)&pup, g_pu);
    cudaGetSymbolAddress((void**)&pvp, g_pv);

    cudaFuncSetAttribute(k_fused, cudaFuncAttributeMaxDynamicSharedMemorySize, 196608);
    cudaFuncSetAttribute(k_prep, cudaFuncAttributeMaxDynamicSharedMemorySize, 98304);
    cudaFuncSetAttribute(k_cand, cudaFuncAttributeMaxDynamicSharedMemorySize, CAND_SMEM_FLOATS * 4);

    // 1: zero state
    k_zero<<<(Nn + 255) / 256, 256>>>();
    // 2: degree count
    k_count<<<1024, 256>>>(dst, E);
    // 3: scan + fill (single pass)
    k_scanfill<<<NB_SCAN, 1024>>>(src, dst, E);
    // 4: layer 0 (profiled position)
    k_fused<<<(Nn + 31) / 32, 256, 196608>>>(x, ws0, wn0, b0, ga0, be0, rm0, rv0, h0p, 0);
    // 5: layer 1 (+ nan_to_num)
    k_fused<<<(Nn + 31) / 32, 256, 196608>>>(h0p, ws1, wn1, b1, ga1, be1, rm1, rv1, h1p, 1);
    // 6: MLP layer0 hoisted to node level
    k_prep<<<(Nn + 31) / 32, 256, 98304>>>(h1p, mw0, pup, pvp);
    // 7: candidate tail -> y
    k_cand<<<(C + 63) / 64, 256, CAND_SMEM_FLOATS * 4>>>(pup, pvp, cu, cv, cf, mw0, mb0, mw1, mb1, mw2, mb2, y, C);
    // 8,9: softmax
    k_softA<<<128, 256>>>(y, C);
    k_softFin<<<256, 256>>>(y, soft, C);
}